// round 16
// baseline (speedup 1.0000x reference)
#include <cuda_runtime.h>

#define THREADS 128
#define NW 4             // warps per block
#define NBLOCKS_SIG 2048 // 8192 half-path warps (2 per path)
#define DXSTRIDE 16      // floats/step: 5 dup pairs + pad + 4 scalars, 64B
#define DXROW (64 * DXSTRIDE + 16)

// Signature layout (d=5, depth 4): L1 [0,5) L2 [5,30) L3 [30,155) L4 [155,780)
__device__ double g_acc[2][784];
__device__ float  g_half[8192 * 784];   // per half-path signature (zero-padded tail)

typedef unsigned long long ull;

__device__ __forceinline__ ull pk2(float lo, float hi) {
    ull r; asm("mov.b64 %0, {%1,%2};" : "=l"(r) : "f"(lo), "f"(hi)); return r;
}
__device__ __forceinline__ void unpk2(ull v, float& a, float& b) {
    asm("mov.b64 {%0,%1}, %2;" : "=f"(a), "=f"(b) : "l"(v));
}
__device__ __forceinline__ ull fma2v(ull a, ull b, ull c) {
    ull d; asm("fma.rn.f32x2 %0, %1, %2, %3;" : "=l"(d) : "l"(a), "l"(b), "l"(c));
    return d;
}

// ---- kernel 1: signature of one HALF path per warp (no cross-warp traffic) --
__global__ void __launch_bounds__(THREADS, 6) sig_half_kernel(
    const float* __restrict__ xin,
    const float* __restrict__ yin,
    const float* __restrict__ sigma)
{
    __shared__ __align__(16) float dxs[NW][DXROW];
    __shared__ float sstage[NW][784];

    const int tid  = threadIdx.x;
    const int lane = tid & 31;
    const int wib  = tid >> 5;
    const int W    = blockIdx.x * NW + wib;  // half-unit id 0..8191
    const int p    = W >> 1;                 // path id 0..4095
    const int half = W & 1;                  // 0: steps [0,64), 1: [64,127)
    const int set  = p >> 11;
    const int bidx = p & 2047;

    float* dx = dxs[wib];
    const float* path = (set == 0 ? xin : yin) + (size_t)bidx * 640;
    const int nsteps = half ? 63 : 64;
    const int pbase  = half ? 320 : 0;

    const float sc1 = (set == 0) ? __ldg(sigma + 0) : 1.0f;
    const float sc2 = (set == 0) ? __ldg(sigma + 1) : 1.0f;
    const float sc3 = (set == 0) ? __ldg(sigma + 2) : 1.0f;
    const float sc4 = (set == 0) ? __ldg(sigma + 3) : 1.0f;

    for (int i = lane; i < 5 * nsteps; i += 32) {
        int t = i / 5;
        int c = i - 5 * t;
        float s = (c == 0) ? 1.0f : (c == 1) ? sc1 : (c == 2) ? sc2
                : (c == 3) ? sc3 : sc4;
        float v = (path[pbase + i + 5] - path[pbase + i]) * s;
        *reinterpret_cast<ull*>(&dx[DXSTRIDE * t + 2 * c]) = pk2(v, v);
        if (c < 4) dx[DXSTRIDE * t + 12 + c] = v;
    }
    __syncwarp();

    // lane = level-2 index ab (lanes 0..24 active; 25..31 clone lane 24)
    const int lc = (lane < 25) ? lane : 24;
    const int a  = lc / 5;
    const int b  = lc - 5 * a;
    const int offa = (a < 4) ? (12 + a) : 8;
    const int offb = (b < 4) ? (12 + b) : 8;

    float s1 = 0.f, s2 = 0.f, s3_4 = 0.f, s4C4 = 0.f;
    ull s3_01 = 0, s3_23 = 0, s4C01 = 0, s4C23 = 0;
    ull s4A[5], s4B[5];
#pragma unroll
    for (int e = 0; e < 5; ++e) { s4A[e] = 0ULL; s4B[e] = 0ULL; }

    float dxa = dx[offa];
    float dxb = dx[offb];

    for (int t = 0; t < nsteps; ++t) {
        const float* dxt = dx + DXSTRIDE * t;
        const float dxa_n = dxt[DXSTRIDE + offa];   // pad in-bounds at last t
        const float dxb_n = dxt[DXSTRIDE + offb];

        const ulonglong2 D01 = *reinterpret_cast<const ulonglong2*>(dxt + 0);
        const ulonglong2 D23 = *reinterpret_cast<const ulonglong2*>(dxt + 4);
        const ull D0 = D01.x, D1 = D01.y, D2 = D23.x, D3 = D23.y;
        const ull D4 = *reinterpret_cast<const ull*>(dxt + 8);
        const float4 sq = *reinterpret_cast<const float4*>(dxt + 12);
        float d4, j_; unpk2(D4, d4, j_);
        const ull d01 = pk2(sq.x, sq.y);
        const ull d23 = pk2(sq.z, sq.w);

        const float a1 = fmaf(dxa, 0.25f,      s1);
        const float c1 = fmaf(dxa, (1.f/3.f),  s1);
        const float e1 = fmaf(dxa, 0.5f,       s1);
        s1 += dxa;
        const float a2  = fmaf(a1 * (1.f/3.f), dxb, s2);
        const float a2h = 0.5f * a2;
        const float b2  = fmaf(c1 * 0.5f, dxb, s2);
        s2 = fmaf(e1, dxb, s2);

        const ull a2hd = pk2(a2h, a2h);
        const ull b2d  = pk2(b2,  b2);

        const ull a3_01 = fma2v(a2hd, d01, s3_01);
        const ull a3_23 = fma2v(a2hd, d23, s3_23);
        s3_01 = fma2v(b2d, d01, s3_01);
        s3_23 = fma2v(b2d, d23, s3_23);
        const float a3_4 = fmaf(a2h, d4, s3_4);
        s3_4 = fmaf(b2, d4, s3_4);

        s4A[0] = fma2v(a3_01, D0, s4A[0]);
        s4A[1] = fma2v(a3_01, D1, s4A[1]);
        s4A[2] = fma2v(a3_01, D2, s4A[2]);
        s4A[3] = fma2v(a3_01, D3, s4A[3]);
        s4A[4] = fma2v(a3_01, D4, s4A[4]);
        s4B[0] = fma2v(a3_23, D0, s4B[0]);
        s4B[1] = fma2v(a3_23, D1, s4B[1]);
        s4B[2] = fma2v(a3_23, D2, s4B[2]);
        s4B[3] = fma2v(a3_23, D3, s4B[3]);
        s4B[4] = fma2v(a3_23, D4, s4B[4]);
        const ull a3_4d = pk2(a3_4, a3_4);
        s4C01 = fma2v(a3_4d, d01, s4C01);
        s4C23 = fma2v(a3_4d, d23, s4C23);
        s4C4  = fmaf(a3_4, d4, s4C4);

        dxa = dxa_n;
        dxb = dxb_n;
    }

    // scatter to this warp's smem row (unique writers, no atomics)
    float* st = sstage[wib];
    if (lane < 25) {
        if (b == 0) st[a] = s1;
        st[5 + lane] = s2;
        float v0, v1, v2, v3;
        unpk2(s3_01, v0, v1); unpk2(s3_23, v2, v3);
        const int b3 = 30 + 5 * lane;
        st[b3 + 0] = v0; st[b3 + 1] = v1; st[b3 + 2] = v2;
        st[b3 + 3] = v3; st[b3 + 4] = s3_4;
        const int b4 = 155 + 25 * lane;
#pragma unroll
        for (int e = 0; e < 5; ++e) {
            float x0, x1, y0, y1;
            unpk2(s4A[e], x0, x1);
            unpk2(s4B[e], y0, y1);
            st[b4 + 0  + e] = x0;
            st[b4 + 5  + e] = x1;
            st[b4 + 10 + e] = y0;
            st[b4 + 15 + e] = y1;
        }
        float z0, z1, z2, z3;
        unpk2(s4C01, z0, z1); unpk2(s4C23, z2, z3);
        st[b4 + 20] = z0; st[b4 + 21] = z1; st[b4 + 22] = z2;
        st[b4 + 23] = z3; st[b4 + 24] = s4C4;
    }
    __syncwarp();

    // coalesced copy to this half-unit's global slice
    float* dst = g_half + (size_t)W * 784;
    for (int i = lane; i < 780; i += 32) dst[i] = st[i];
}

// ---- kernel 2: Chen combine A (x) B per path, accumulate into g_acc --------
// Uniform per-component form: out = A[j]+B[j] + sum_{k<3} A[ta_k]*B[tb_k],
// with unused terms pointing at zero slot 783 (g_half pads & smem pads = 0).
#define CPATHS 16   // paths per block; 256 blocks total, set-uniform
__global__ void __launch_bounds__(256) combine_kernel() {
    __shared__ float As[784], Bs[784];

    const int tid  = threadIdx.x;
    const int pbase = blockIdx.x * CPATHS;
    const int set   = pbase >> 11;           // uniform (16 | 2048)

    // decode this thread's (up to) 4 components once
    int jv[4], t1a[4], t1b[4], t2a[4], t2b[4], t3a[4], t3b[4];
    bool valid[4];
#pragma unroll
    for (int k = 0; k < 4; ++k) {
        int j = tid + 256 * k;
        valid[k] = (j < 780);
        if (!valid[k]) j = 783;
        jv[k] = j;
        int u1a = 783, u1b = 783, u2a = 783, u2b = 783, u3a = 783, u3b = 783;
        if (j >= 5 && j < 30) {
            int ab = j - 5, a = ab / 5, b = ab - 5 * a;
            u1a = a; u1b = b;
        } else if (j >= 30 && j < 155) {
            int q = j - 30, a = q / 25, r = q - 25 * a, b = r / 5, c = r - 5 * b;
            u1a = a;          u1b = 5 + r;
            u2a = 5 + 5*a + b; u2b = c;
        } else if (j >= 155 && j < 780) {
            int q = j - 155, w = q / 125, r = q - 125 * w;
            int x = r / 25, r2 = r - 25 * x, y = r2 / 5, z = r2 - 5 * y;
            u1a = w;                 u1b = 30 + r;
            u2a = 5 + 5*w + x;       u2b = 5 + 5*y + z;
            u3a = 30 + 25*w + 5*x + y; u3b = z;
        }
        t1a[k] = u1a; t1b[k] = u1b;
        t2a[k] = u2a; t2b[k] = u2b;
        t3a[k] = u3a; t3b[k] = u3b;
    }

    double acc[4] = {0.0, 0.0, 0.0, 0.0};

    for (int pp = 0; pp < CPATHS; ++pp) {
        const int p = pbase + pp;
        const float* Ag = g_half + (size_t)(2 * p) * 784;
        const float* Bg = g_half + (size_t)(2 * p + 1) * 784;
        for (int i = tid; i < 784; i += 256) {
            As[i] = (i < 780) ? Ag[i] : 0.0f;
            Bs[i] = (i < 780) ? Bg[i] : 0.0f;
        }
        __syncthreads();
#pragma unroll
        for (int k = 0; k < 4; ++k) {
            float o = As[jv[k]] + Bs[jv[k]];
            o = fmaf(As[t1a[k]], Bs[t1b[k]], o);
            o = fmaf(As[t2a[k]], Bs[t2b[k]], o);
            o = fmaf(As[t3a[k]], Bs[t3b[k]], o);
            acc[k] += (double)o;
        }
        __syncthreads();
    }

#pragma unroll
    for (int k = 0; k < 4; ++k)
        if (valid[k]) atomicAdd(&g_acc[set][jv[k]], acc[k]);
}

// ---- kernel 3: final norm; resets g_acc for the next graph replay ----------
__global__ void finalize_kernel(float* out) {
    __shared__ double wred[32];
    const int tid  = threadIdx.x;     // 1024 threads = 32 warps
    const int lane = tid & 31;
    const int wid  = tid >> 5;

    double s = 0.0;
    if (tid < 780) {
        double d = (g_acc[0][tid] - g_acc[1][tid]) * (1.0 / 2048.0);
        s = d * d;
    }
#pragma unroll
    for (int k = 16; k > 0; k >>= 1)
        s += __shfl_down_sync(0xffffffffu, s, k);
    if (lane == 0) wred[wid] = s;
    __syncthreads();
    if (wid == 0) {
        double v = wred[lane];
#pragma unroll
        for (int k = 16; k > 0; k >>= 1)
            v += __shfl_down_sync(0xffffffffu, v, k);
        if (lane == 0) out[0] = (float)v;
    }
    for (int e = tid; e < 2 * 784; e += 1024)
        ((double*)g_acc)[e] = 0.0;
}

extern "C" void kernel_launch(void* const* d_in, const int* in_sizes, int n_in,
                              void* d_out, int out_size) {
    (void)in_sizes; (void)n_in; (void)out_size;
    const float* x     = (const float*)d_in[0];
    const float* y     = (const float*)d_in[1];
    const float* sigma = (const float*)d_in[2];
    float* out = (float*)d_out;

    sig_half_kernel<<<NBLOCKS_SIG, THREADS>>>(x, y, sigma);
    combine_kernel<<<4096 / CPATHS, 256>>>();
    finalize_kernel<<<1, 1024>>>(out);
}

// round 17
// speedup vs baseline: 1.6430x; 1.6430x over previous
#include <cuda_runtime.h>

#define THREADS 128
#define NW 4           // warps per block, one warp per path
#define NBLOCKS 1024   // 4096 paths
#define DXSTRIDE 16    // floats/step: 5 dup pairs (10) + pad + 4 scalars, 64B
#define DXROW (129 * DXSTRIDE)  // +row 127 zeroed (identity step), +row 128 in-bounds

// Signature layout (d=5, depth 4): L1 [0,5) L2 [5,30) L3 [30,155) L4 [155,780)
__device__ double g_acc[2][784];

typedef unsigned long long ull;

__device__ __forceinline__ ull pk2(float lo, float hi) {
    ull r; asm("mov.b64 %0, {%1,%2};" : "=l"(r) : "f"(lo), "f"(hi)); return r;
}
__device__ __forceinline__ void unpk2(ull v, float& a, float& b) {
    asm("mov.b64 {%0,%1}, %2;" : "=f"(a), "=f"(b) : "l"(v));
}
__device__ __forceinline__ ull fma2v(ull a, ull b, ull c) {
    ull d; asm("fma.rn.f32x2 %0, %1, %2, %3;" : "=l"(d) : "l"(a), "l"(b), "l"(c));
    return d;
}

__global__ void __launch_bounds__(THREADS, 6) sig_kernel(
    const float* __restrict__ xin,
    const float* __restrict__ yin,
    const float* __restrict__ sigma)
{
    // per-warp increments, stride 16 floats (64B) per step:
    //   [0..9]  : (d_c, d_c) duplicate pairs  [12..15]: scalars d0..d3
    __shared__ __align__(16) float dxs[NW][DXROW];
    __shared__ float shacc[784];

    const int tid  = threadIdx.x;
    const int lane = tid & 31;
    const int wib  = tid >> 5;
    const int gw   = blockIdx.x * NW + wib;  // path id 0..4095
    const int set  = gw >> 11;               // 0: x (sigma-scaled), 1: y
    const int bidx = gw & 2047;

    for (int i = tid; i < 784; i += THREADS) shacc[i] = 0.0f;
    __syncthreads();

    float* dx = dxs[wib];
    const float* path = (set == 0 ? xin : yin) + (size_t)bidx * 640;

    const float sc1 = (set == 0) ? __ldg(sigma + 0) : 1.0f;
    const float sc2 = (set == 0) ? __ldg(sigma + 1) : 1.0f;
    const float sc3 = (set == 0) ? __ldg(sigma + 2) : 1.0f;
    const float sc4 = (set == 0) ? __ldg(sigma + 3) : 1.0f;

    // stage: dup pair always; scalar copy only for c<4; zero row 127 (identity)
    for (int i = lane; i < 635; i += 32) {
        int t = i / 5;
        int c = i - 5 * t;
        float s = (c == 0) ? 1.0f : (c == 1) ? sc1 : (c == 2) ? sc2
                : (c == 3) ? sc3 : sc4;
        float v = (path[i + 5] - path[i]) * s;
        *reinterpret_cast<ull*>(&dx[DXSTRIDE * t + 2 * c]) = pk2(v, v);
        if (c < 4) dx[DXSTRIDE * t + 12 + c] = v;
    }
    if (lane < 16) dx[DXSTRIDE * 127 + lane] = 0.0f;   // phantom step = identity
    __syncwarp();

    // --- lane = level-2 index ab (lanes 0..24 active; 25..31 clone lane 24) --
    const int lc = (lane < 25) ? lane : 24;
    const int a  = lc / 5;
    const int b  = lc - 5 * a;
    const int offa = (a < 4) ? (12 + a) : 8;   // d4 scalar lives at dup slot 8
    const int offb = (b < 4) ? (12 + b) : 8;

    // state: S1[a], S2[ab], S3[5ab+c] (c-packed), S4[25ab+5c+e]
    float s1 = 0.f, s2 = 0.f, s3_4 = 0.f, s4C4 = 0.f;
    ull s3_01 = 0, s3_23 = 0, s4C01 = 0, s4C23 = 0;
    ull s4A[5], s4B[5];
#pragma unroll
    for (int e = 0; e < 5; ++e) { s4A[e] = 0ULL; s4B[e] = 0ULL; }

    // --- software pipeline: a2hd/b2d (step t's helpers) computed one iter
    // ahead; dxa_c/dxb_c hold step t+1's chain-head scalars -------------------
    ull a2hd, b2d;
    float dxa_c, dxb_c;
    {
        // helpers(0) from S=0 + L1/L2 update for step 0
        const float dxa0 = dx[offa];
        const float dxb0 = dx[offb];
        const float a1 = dxa0 * 0.25f;
        const float c1 = dxa0 * (1.f/3.f);
        const float e1 = dxa0 * 0.5f;
        s1 = dxa0;
        const float a2  = (a1 * (1.f/3.f)) * dxb0;
        const float a2h = 0.5f * a2;
        const float b2  = (c1 * 0.5f) * dxb0;
        s2 = e1 * dxb0;
        a2hd = pk2(a2h, a2h);
        b2d  = pk2(b2,  b2);
        dxa_c = dx[DXSTRIDE + offa];   // step 1
        dxb_c = dx[DXSTRIDE + offb];
    }

    for (int t = 0; t < 127; ++t) {
        const float* dxt = dx + DXSTRIDE * t;

        // step t's channel data
        const ulonglong2 D01 = *reinterpret_cast<const ulonglong2*>(dxt + 0);
        const ulonglong2 D23 = *reinterpret_cast<const ulonglong2*>(dxt + 4);
        const ull D0 = D01.x, D1 = D01.y, D2 = D23.x, D3 = D23.y;
        const ull D4 = *reinterpret_cast<const ull*>(dxt + 8);
        const float4 sq = *reinterpret_cast<const float4*>(dxt + 12);
        float d4, j_; unpk2(D4, d4, j_);
        const ull d01 = pk2(sq.x, sq.y);
        const ull d23 = pk2(sq.z, sq.w);
        // preload step t+2 chain heads (t=126 reads in-bounds row 128, dead)
        const float dxa_n = dxt[2 * DXSTRIDE + offa];
        const float dxb_n = dxt[2 * DXSTRIDE + offb];

        // level-3/4 of step t — a2hd/b2d ready at iteration entry
        const ull a3_01 = fma2v(a2hd, d01, s3_01);
        const ull a3_23 = fma2v(a2hd, d23, s3_23);
        s3_01 = fma2v(b2d, d01, s3_01);
        s3_23 = fma2v(b2d, d23, s3_23);
        float a2h_s, b2_s; unpk2(a2hd, a2h_s, j_);
        float b2s2, j2_;   unpk2(b2d,  b2s2,  j2_);
        const float a3_4 = fmaf(a2h_s, d4, s3_4);
        s3_4 = fmaf(b2s2, d4, s3_4);

        s4A[0] = fma2v(a3_01, D0, s4A[0]);
        s4A[1] = fma2v(a3_01, D1, s4A[1]);
        s4A[2] = fma2v(a3_01, D2, s4A[2]);
        s4A[3] = fma2v(a3_01, D3, s4A[3]);
        s4A[4] = fma2v(a3_01, D4, s4A[4]);
        s4B[0] = fma2v(a3_23, D0, s4B[0]);
        s4B[1] = fma2v(a3_23, D1, s4B[1]);
        s4B[2] = fma2v(a3_23, D2, s4B[2]);
        s4B[3] = fma2v(a3_23, D3, s4B[3]);
        s4B[4] = fma2v(a3_23, D4, s4B[4]);
        const ull a3_4d = pk2(a3_4, a3_4);
        s4C01 = fma2v(a3_4d, d01, s4C01);
        s4C23 = fma2v(a3_4d, d23, s4C23);
        s4C4  = fmaf(a3_4, d4, s4C4);

        // helpers(t+1) + L1/L2 update (independent of L3/L4 above; t=126 uses
        // the zeroed row 127 -> s1/s2 updates are identity, helpers dead)
        const float a1 = fmaf(dxa_c, 0.25f,      s1);
        const float c1 = fmaf(dxa_c, (1.f/3.f),  s1);
        const float e1 = fmaf(dxa_c, 0.5f,       s1);
        s1 += dxa_c;
        const float a2  = fmaf(a1 * (1.f/3.f), dxb_c, s2);
        const float a2h = 0.5f * a2;
        const float b2  = fmaf(c1 * 0.5f, dxb_c, s2);
        s2 = fmaf(e1, dxb_c, s2);
        a2hd = pk2(a2h, a2h);
        b2d  = pk2(b2,  b2);

        dxa_c = dxa_n;
        dxb_c = dxb_n;
    }

    // --- block reduction: shared float atomics (distinct addrs per lane) ---
    if (lane < 25) {
        if (b == 0) atomicAdd(&shacc[a], s1);          // lanes 0,5,10,15,20
        atomicAdd(&shacc[5 + lane], s2);
        float v0, v1, v2, v3;
        unpk2(s3_01, v0, v1); unpk2(s3_23, v2, v3);
        const int b3 = 30 + 5 * lane;
        atomicAdd(&shacc[b3 + 0], v0);
        atomicAdd(&shacc[b3 + 1], v1);
        atomicAdd(&shacc[b3 + 2], v2);
        atomicAdd(&shacc[b3 + 3], v3);
        atomicAdd(&shacc[b3 + 4], s3_4);
        const int b4 = 155 + 25 * lane;
#pragma unroll
        for (int e = 0; e < 5; ++e) {
            float x0, x1, y0, y1;
            unpk2(s4A[e], x0, x1);
            unpk2(s4B[e], y0, y1);
            atomicAdd(&shacc[b4 + 0  + e], x0);
            atomicAdd(&shacc[b4 + 5  + e], x1);
            atomicAdd(&shacc[b4 + 10 + e], y0);
            atomicAdd(&shacc[b4 + 15 + e], y1);
        }
        float z0, z1, z2, z3;
        unpk2(s4C01, z0, z1); unpk2(s4C23, z2, z3);
        atomicAdd(&shacc[b4 + 20], z0);
        atomicAdd(&shacc[b4 + 21], z1);
        atomicAdd(&shacc[b4 + 22], z2);
        atomicAdd(&shacc[b4 + 23], z3);
        atomicAdd(&shacc[b4 + 24], s4C4);
    }
    __syncthreads();

    // global: double atomics, 1024 contributions per address
    for (int i = tid; i < 780; i += THREADS)
        atomicAdd(&g_acc[set][i], (double)shacc[i]);
}

// one element per thread + warp-shuffle reduce; resets g_acc for next replay
__global__ void finalize_kernel(float* out) {
    __shared__ double wred[32];
    const int tid  = threadIdx.x;     // 1024 threads = 32 warps
    const int lane = tid & 31;
    const int wid  = tid >> 5;

    double s = 0.0;
    if (tid < 780) {
        double d = (g_acc[0][tid] - g_acc[1][tid]) * (1.0 / 2048.0);
        s = d * d;
    }
#pragma unroll
    for (int k = 16; k > 0; k >>= 1)
        s += __shfl_down_sync(0xffffffffu, s, k);
    if (lane == 0) wred[wid] = s;
    __syncthreads();
    if (wid == 0) {
        double v = wred[lane];
#pragma unroll
        for (int k = 16; k > 0; k >>= 1)
            v += __shfl_down_sync(0xffffffffu, v, k);
        if (lane == 0) out[0] = (float)v;
    }
    for (int e = tid; e < 2 * 784; e += 1024)
        ((double*)g_acc)[e] = 0.0;
}

extern "C" void kernel_launch(void* const* d_in, const int* in_sizes, int n_in,
                              void* d_out, int out_size) {
    (void)in_sizes; (void)n_in; (void)out_size;
    const float* x     = (const float*)d_in[0];
    const float* y     = (const float*)d_in[1];
    const float* sigma = (const float*)d_in[2];
    float* out = (float*)d_out;

    sig_kernel<<<NBLOCKS, THREADS>>>(x, y, sigma);
    finalize_kernel<<<1, 1024>>>(out);
}